// round 6
// baseline (speedup 1.0000x reference)
#include <cuda_runtime.h>
#include <cuda_fp16.h>
#include <math.h>

// x (32, 1, 720, 1024) f32 -> out (32, 1, 512, 512) f32
// out[z,y,xp] = (pi/720) * sum_v lerp(x[z,0,v,:], t),  t = xf*cos + yf*sin + 511.5
// t in [150.2, 872.8] => always in-bounds for nDct=1024.
//
// R5: fp16 z-oct cells + HALF-DOMAIN accumulation (2 HFMA2 per half2-pair of z)
// flushed to f32 every NF=4 views. Cuts consumer issue from 40 to ~22 slots
// per r-step. Windowed staging (80 cells/view), f32 final accumulation.

#define NV   720
#define ND   1024
#define NVND (NV * ND)
#define NXI  512
#define NYI  512
#define WIN  80     // staged window cells per view (max span ~67 + slack)
#define RY   4      // r-steps per thread (y stride 4) -> 16 y rows per warp
#define ZC   8      // z-slices per cell
#define NF   4      // views per half-accumulator flush window

__device__ float g_cos[NV];
__device__ float g_sin[NV];

__global__ void init_trig_kernel() {
    int v = blockIdx.x * blockDim.x + threadIdx.x;
    if (v < NV) {
        float th = (float)v * (float)(M_PI / (double)NV);
        g_cos[v] = cosf(th);
        g_sin[v] = sinf(th);
    }
}

// Must be computed identically by stager and consumers (same FP ops => it is).
__device__ __forceinline__ int calc_dmin(float c, float s, float xfmin, float yf0) {
    float xsel = (c >= 0.0f) ? xfmin : (xfmin + 63.0f);   // 64-wide x tile
    float tmin = fmaf(xsel, c, fmaf(yf0, s, 511.5f));     // s >= 0 on [0,pi)
    return (int)tmin - 1;                                 // tmin > 0: trunc==floor; -1 ulp guard
}

__global__ __launch_bounds__(256, 3) void backproject_kernel(
    const float* __restrict__ x, float* __restrict__ out)
{
    __shared__ uint4 cell[2][WIN];           // half8 z-oct cells, double-buffered (2.5 KB)
    __shared__ float s_cos[NV], s_sin[NV];   // 5.76 KB

    const int tid  = threadIdx.x;            // 256 threads = 8 warps
    const int lane = tid & 31;
    const int wrp  = tid >> 5;
    const int lx   = lane & 7;               // 8 x per warp
    const int ly   = lane >> 3;              // 4 y per warp

    for (int i = tid; i < NV; i += 256) { s_cos[i] = g_cos[i]; s_sin[i] = g_sin[i]; }

    const int xg = blockIdx.x * 64 + wrp * 8 + lx;   // 8 x-tiles of 64
    const int yb = blockIdx.y * 16 + ly;             // 32 y-tiles of 16; thread rows yb + 4r
    const int zq = blockIdx.z * ZC;                  // 4 z-octs

    const float xf    = (float)xg - 255.5f;
    const float ybf   = (float)yb - 255.5f;
    const float xfmin = (float)(blockIdx.x * 64) - 255.5f;
    const float yf0   = (float)(blockIdx.y * 16) - 255.5f;

    float accf[RY][ZC];                      // final f32 accumulators
#pragma unroll
    for (int r = 0; r < RY; r++)
#pragma unroll
        for (int zz = 0; zz < ZC; zz++) accf[r][zz] = 0.0f;

    __half2 acch[RY][4];                     // half window accumulators (z pairs)
#pragma unroll
    for (int r = 0; r < RY; r++)
#pragma unroll
        for (int p = 0; p < 4; p++) acch[r][p] = __float2half2_rn(0.0f);

    const __half2 ONE2 = __float2half2_rn(1.0f);

    // shared-window base as 32-bit shared address for asm LDS
    unsigned int cell_base;
    asm("{ .reg .u64 t; cvta.to.shared.u64 t, %1; cvt.u32.u64 %0, t; }"
        : "=r"(cell_base) : "l"((const void*)cell));

    // Staging role: 160 threads, each owns (cell sc, z-half zh) -> 4 z values.
    const int st_on = (tid < 160);
    const int zh    = (tid >= 80) ? 1 : 0;
    const int sc    = tid - zh * 80;              // cell index 0..79
    const float* __restrict__ gsl = x + (size_t)(zq + zh * 4) * NVND;

    // Prefetch view 0 window (theta=0: c=1, s=0 exactly)
    float r0 = 0.f, r1 = 0.f, r2 = 0.f, r3 = 0.f;
    if (st_on) {
        int dm = calc_dmin(1.0f, 0.0f, xfmin, yf0);
        const float* g = gsl + dm + sc;           // view 0 row offset = 0
        r0 = g[0]; r1 = g[NVND]; r2 = g[2 * NVND]; r3 = g[3 * NVND];
    }

    for (int v = 0; v < NV; v++) {
        const int buf = v & 1;
        if (st_on) {
            __half2 h01 = __floats2half2_rn(r0, r1);
            __half2 h23 = __floats2half2_rn(r2, r3);
            unsigned u01 = *reinterpret_cast<unsigned*>(&h01);
            unsigned u23 = *reinterpret_cast<unsigned*>(&h23);
            *reinterpret_cast<uint2*>(
                reinterpret_cast<unsigned*>(&cell[buf][sc]) + zh * 2) = make_uint2(u01, u23);
        }
        __syncthreads();   // single sync per view; double buffering covers WAR

        if (v + 1 < NV && st_on) {
            float c1 = s_cos[v + 1], s1 = s_sin[v + 1];
            int dm = calc_dmin(c1, s1, xfmin, yf0);
            const float* g = gsl + (size_t)(v + 1) * ND + dm + sc;
            r0 = g[0]; r1 = g[NVND]; r2 = g[2 * NVND]; r3 = g[3 * NVND];
        }

        const float c = s_cos[v];
        const float s = s_sin[v];
        const int dmin = calc_dmin(c, s, xfmin, yf0);
        // u = t - dmin, in [0, WIN-2) for every pixel of this tile
        float u = fmaf(xf, c, fmaf(ybf, s, 511.5f - (float)dmin));
        const float s4 = 4.0f * s;                 // y stride 4 rows per r-step
        const unsigned int base = cell_base + (buf ? (unsigned)(WIN * 16) : 0u);

#pragma unroll
        for (int r = 0; r < RY; r++) {
            int   i0 = (int)u;                     // u > 0: trunc == floor
            float w  = u - (float)i0;
            __half2 wh2  = __float2half2_rn(w);
            __half2 w0h2 = __hsub2(ONE2, wh2);
            unsigned int a0 = base + (unsigned)i0 * 16u;
            uint4 A, B;
            asm("ld.shared.v4.b32 {%0,%1,%2,%3}, [%4];"
                : "=r"(A.x), "=r"(A.y), "=r"(A.z), "=r"(A.w) : "r"(a0));
            asm("ld.shared.v4.b32 {%0,%1,%2,%3}, [%4 + 16];"
                : "=r"(B.x), "=r"(B.y), "=r"(B.z), "=r"(B.w) : "r"(a0));
#pragma unroll
            for (int p = 0; p < 4; p++) {
                unsigned ua = (p == 0) ? A.x : (p == 1) ? A.y : (p == 2) ? A.z : A.w;
                unsigned ub = (p == 0) ? B.x : (p == 1) ? B.y : (p == 2) ? B.z : B.w;
                __half2 ha = *reinterpret_cast<__half2*>(&ua);
                __half2 hb = *reinterpret_cast<__half2*>(&ub);
                acch[r][p] = __hfma2(ha, w0h2, acch[r][p]);
                acch[r][p] = __hfma2(hb, wh2,  acch[r][p]);
            }
            u += s4;
        }

        // Flush half window accumulators into f32 every NF views
        if ((v & (NF - 1)) == (NF - 1)) {
#pragma unroll
            for (int r = 0; r < RY; r++)
#pragma unroll
                for (int p = 0; p < 4; p++) {
                    float2 f = __half22float2(acch[r][p]);
                    accf[r][2 * p]     += f.x;
                    accf[r][2 * p + 1] += f.y;
                    acch[r][p] = __float2half2_rn(0.0f);
                }
        }
    }

    const float scale = (float)(M_PI / (double)NV);
#pragma unroll
    for (int r = 0; r < RY; r++) {
        const int y = yb + 4 * r;
#pragma unroll
        for (int zz = 0; zz < ZC; zz++) {
            out[((size_t)(zq + zz) * NYI + y) * NXI + xg] = accf[r][zz] * scale;
        }
    }
}

extern "C" void kernel_launch(void* const* d_in, const int* in_sizes, int n_in,
                              void* d_out, int out_size)
{
    const float* x   = (const float*)d_in[0];
    float*       out = (float*)d_out;

    init_trig_kernel<<<(NV + 255) / 256, 256>>>();

    dim3 grid(8, 32, 4);   // x-tiles, y-tiles, z-octs = 1024 CTAs
    backproject_kernel<<<grid, 256>>>(x, out);
}

// round 7
// speedup vs baseline: 1.7879x; 1.7879x over previous
#include <cuda_runtime.h>
#include <cuda_fp16.h>
#include <math.h>

// x (32, 1, 720, 1024) f32 -> out (32, 1, 512, 512) f32
// out[z,y,xp] = (pi/720) * sum_v lerp(x[z,0,v,:], t),  t = xf*cos + yf*sin + 511.5
// t in [150.2, 872.8] => always in-bounds for nDct=1024.
//
// R6 = R4 base (fp16 z-oct cells, windowed staging, f32 accumulators) with the
// lerp computed in half precision (HSUB2 + HFMA2 per z-pair) and only the
// lerped result converted to f32 (8 F2F per r-step instead of 16).
// NO loop-carried half state (R5's regression came from persistent half2
// accumulator chains).

#define NV   720
#define ND   1024
#define NVND (NV * ND)
#define NXI  512
#define NYI  512
#define WIN  80     // staged window cells per view (max span ~67 + slack)
#define RY   4      // r-steps per thread (y stride 4) -> 16 y rows per warp
#define ZC   8      // z-slices per cell

__device__ float g_cos[NV];
__device__ float g_sin[NV];

__global__ void init_trig_kernel() {
    int v = blockIdx.x * blockDim.x + threadIdx.x;
    if (v < NV) {
        float th = (float)v * (float)(M_PI / (double)NV);
        g_cos[v] = cosf(th);
        g_sin[v] = sinf(th);
    }
}

// Must be computed identically by stager and consumers (same FP ops => it is).
__device__ __forceinline__ int calc_dmin(float c, float s, float xfmin, float yf0) {
    float xsel = (c >= 0.0f) ? xfmin : (xfmin + 63.0f);   // 64-wide x tile
    float tmin = fmaf(xsel, c, fmaf(yf0, s, 511.5f));     // s >= 0 on [0,pi)
    return (int)tmin - 1;                                 // tmin > 0: trunc==floor; -1 ulp guard
}

__global__ __launch_bounds__(256, 3) void backproject_kernel(
    const float* __restrict__ x, float* __restrict__ out)
{
    __shared__ uint4 cell[2][WIN];           // half8 z-oct cells, double-buffered (2.5 KB)
    __shared__ float s_cos[NV], s_sin[NV];   // 5.76 KB

    const int tid  = threadIdx.x;            // 256 threads = 8 warps
    const int lane = tid & 31;
    const int wrp  = tid >> 5;
    const int lx   = lane & 7;               // 8 x per warp
    const int ly   = lane >> 3;              // 4 y per warp

    for (int i = tid; i < NV; i += 256) { s_cos[i] = g_cos[i]; s_sin[i] = g_sin[i]; }

    const int xg = blockIdx.x * 64 + wrp * 8 + lx;   // 8 x-tiles of 64
    const int yb = blockIdx.y * 16 + ly;             // 32 y-tiles of 16; thread rows yb + 4r
    const int zq = blockIdx.z * ZC;                  // 4 z-octs

    const float xf    = (float)xg - 255.5f;
    const float ybf   = (float)yb - 255.5f;
    const float xfmin = (float)(blockIdx.x * 64) - 255.5f;
    const float yf0   = (float)(blockIdx.y * 16) - 255.5f;

    float acc[RY][ZC];                       // persistent f32 accumulators
#pragma unroll
    for (int r = 0; r < RY; r++)
#pragma unroll
        for (int zz = 0; zz < ZC; zz++) acc[r][zz] = 0.0f;

    // shared-window base as 32-bit shared address for asm LDS
    unsigned int cell_base;
    asm("{ .reg .u64 t; cvta.to.shared.u64 t, %1; cvt.u32.u64 %0, t; }"
        : "=r"(cell_base) : "l"((const void*)cell));

    // Staging role: 160 threads, each owns (cell sc, z-half zh) -> 4 z values.
    const int st_on = (tid < 160);
    const int zh    = (tid >= 80) ? 1 : 0;
    const int sc    = tid - zh * 80;              // cell index 0..79
    const float* __restrict__ gsl = x + (size_t)(zq + zh * 4) * NVND;

    // Prefetch view 0 window (theta=0: c=1, s=0 exactly)
    float r0 = 0.f, r1 = 0.f, r2 = 0.f, r3 = 0.f;
    if (st_on) {
        int dm = calc_dmin(1.0f, 0.0f, xfmin, yf0);
        const float* g = gsl + dm + sc;           // view 0 row offset = 0
        r0 = g[0]; r1 = g[NVND]; r2 = g[2 * NVND]; r3 = g[3 * NVND];
    }

    for (int v = 0; v < NV; v++) {
        const int buf = v & 1;
        if (st_on) {
            __half2 h01 = __floats2half2_rn(r0, r1);
            __half2 h23 = __floats2half2_rn(r2, r3);
            unsigned u01 = *reinterpret_cast<unsigned*>(&h01);
            unsigned u23 = *reinterpret_cast<unsigned*>(&h23);
            *reinterpret_cast<uint2*>(
                reinterpret_cast<unsigned*>(&cell[buf][sc]) + zh * 2) = make_uint2(u01, u23);
        }
        __syncthreads();   // single sync per view; double buffering covers WAR

        if (v + 1 < NV && st_on) {
            float c1 = s_cos[v + 1], s1 = s_sin[v + 1];
            int dm = calc_dmin(c1, s1, xfmin, yf0);
            const float* g = gsl + (size_t)(v + 1) * ND + dm + sc;
            r0 = g[0]; r1 = g[NVND]; r2 = g[2 * NVND]; r3 = g[3 * NVND];
        }

        const float c = s_cos[v];
        const float s = s_sin[v];
        const int dmin = calc_dmin(c, s, xfmin, yf0);
        // u = t - dmin, in [0, WIN-2) for every pixel of this tile
        float u = fmaf(xf, c, fmaf(ybf, s, 511.5f - (float)dmin));
        const float s4 = 4.0f * s;                 // y stride 4 rows per r-step
        const unsigned int base = cell_base + (buf ? (unsigned)(WIN * 16) : 0u);

#pragma unroll
        for (int r = 0; r < RY; r++) {
            int   i0 = (int)u;                     // u > 0: trunc == floor
            float w  = u - (float)i0;
            __half2 wh2 = __float2half2_rn(w);     // one F2FP (broadcast pack)
            unsigned int a0 = base + (unsigned)i0 * 16u;
            uint4 A, B;
            asm("ld.shared.v4.b32 {%0,%1,%2,%3}, [%4];"
                : "=r"(A.x), "=r"(A.y), "=r"(A.z), "=r"(A.w) : "r"(a0));
            asm("ld.shared.v4.b32 {%0,%1,%2,%3}, [%4 + 16];"
                : "=r"(B.x), "=r"(B.y), "=r"(B.z), "=r"(B.w) : "r"(a0));
#pragma unroll
            for (int p = 0; p < 4; p++) {
                unsigned ua = (p == 0) ? A.x : (p == 1) ? A.y : (p == 2) ? A.z : A.w;
                unsigned ub = (p == 0) ? B.x : (p == 1) ? B.y : (p == 2) ? B.z : B.w;
                __half2 ha = *reinterpret_cast<__half2*>(&ua);
                __half2 hb = *reinterpret_cast<__half2*>(&ub);
                // feed-forward half lerp: l = a + w*(b - a); no persistent half state
                __half2 d  = __hsub2(hb, ha);
                __half2 l  = __hfma2(d, wh2, ha);
                float2 f   = __half22float2(l);
                acc[r][2 * p]     += f.x;
                acc[r][2 * p + 1] += f.y;
            }
            u += s4;
        }
    }

    const float scale = (float)(M_PI / (double)NV);
#pragma unroll
    for (int r = 0; r < RY; r++) {
        const int y = yb + 4 * r;
#pragma unroll
        for (int zz = 0; zz < ZC; zz++) {
            out[((size_t)(zq + zz) * NYI + y) * NXI + xg] = acc[r][zz] * scale;
        }
    }
}

extern "C" void kernel_launch(void* const* d_in, const int* in_sizes, int n_in,
                              void* d_out, int out_size)
{
    const float* x   = (const float*)d_in[0];
    float*       out = (float*)d_out;

    init_trig_kernel<<<(NV + 255) / 256, 256>>>();

    dim3 grid(8, 32, 4);   // x-tiles, y-tiles, z-octs = 1024 CTAs
    backproject_kernel<<<grid, 256>>>(x, out);
}